// round 16
// baseline (speedup 1.0000x reference)
#include <cuda_runtime.h>
#include <cuda_bf16.h>
#include <cstdint>

#define BB 8
#define CC 256
#define NN 2048

typedef __nv_bfloat16 bf16;

// ------------------------- scratch (device globals) -------------------------
__device__ bf16  g_xs [BB * NN * 2 * CC];   // x split  [b][n][hiC|loC]
__device__ bf16  g_Ws [3 * CC * 2 * CC];    // W split rows [q|v|k], [m][hiC|loC]
__device__ float g_bias[3 * CC];            // [q|v|k]
__device__ bf16  g_qs [BB * CC * 2 * NN];   // q split  [b*C+c][hiN|loN]
__device__ bf16  g_vs [BB * CC * 2 * NN];   // v split
__device__ bf16  g_ksT[BB * NN * 2 * CC];   // k^T split [b][n][hiC|loC]
__device__ float g_Mpart[96 * CC * CC];     // split-K partials (12 chunks x 8 b)
__device__ bf16  g_Ms [BB * CC * 2 * CC];   // M split  [b*C+c1][hiC2|loC2]
__device__ float g_xsum[BB * CC];
__device__ float g_spart[BB * CC];

// ------------------------- helpers -------------------------
__device__ __forceinline__ uint32_t smem_u32(const void* p) {
    uint32_t a;
    asm("{ .reg .u64 t; cvta.to.shared.u64 t, %1; cvt.u32.u64 %0, t; }" : "=r"(a) : "l"(p));
    return a;
}

__device__ __forceinline__ void cp_async16(uint32_t saddr, const void* gaddr) {
    asm volatile("cp.async.cg.shared.global [%0], [%1], 16;\n" :: "r"(saddr), "l"(gaddr));
}
__device__ __forceinline__ void cp_commit() {
    asm volatile("cp.async.commit_group;\n" ::: "memory");
}
template <int N>
__device__ __forceinline__ void cp_wait() {
    asm volatile("cp.async.wait_group %0;\n" :: "n"(N) : "memory");
}

__device__ __forceinline__ void ldmx4(unsigned* r, uint32_t addr) {
    asm volatile("ldmatrix.sync.aligned.m8n8.x4.shared.b16 {%0,%1,%2,%3}, [%4];\n"
                 : "=r"(r[0]), "=r"(r[1]), "=r"(r[2]), "=r"(r[3]) : "r"(addr));
}

__device__ __forceinline__ void mma16816(float* c, const unsigned* a,
                                         unsigned b0, unsigned b1) {
    asm volatile(
        "mma.sync.aligned.m16n8k16.row.col.f32.bf16.bf16.f32 "
        "{%0,%1,%2,%3},{%4,%5,%6,%7},{%8,%9},{%0,%1,%2,%3};\n"
        : "+f"(c[0]), "+f"(c[1]), "+f"(c[2]), "+f"(c[3])
        : "r"(a[0]), "r"(a[1]), "r"(a[2]), "r"(a[3]), "r"(b0), "r"(b1));
}

// split-bf16 K'' -> (ka, kb): t0: hi*hi, t1: Ahi*Blo, t2: Alo*Bhi
__device__ __forceinline__ void koffs(int kk, int K, int& ka, int& kb) {
    int term = kk / K;
    int kmod = kk - term * K;
    ka = (term == 2 ? K : 0) + kmod;
    kb = (term == 1 ? K : 0) + kmod;
}

__device__ __forceinline__ void split_store(bf16* row, int n, int lo_off,
                                            float v0, float v1)
{
    __nv_bfloat162 h, l;
    h.x = __float2bfloat16(v0);
    h.y = __float2bfloat16(v1);
    l.x = __float2bfloat16(v0 - __bfloat162float(h.x));
    l.y = __float2bfloat16(v1 - __bfloat162float(h.y));
    *reinterpret_cast<__nv_bfloat162*>(row + n)          = h;
    *reinterpret_cast<__nv_bfloat162*>(row + lo_off + n) = l;
}

// ------------------------- mma.sync GEMM core -------------------------
// BM=128, BN=128, BK=32 bf16, 128 threads (4 warps, 2x2 grid), warp tile
// 64x64 -> each SMEM fragment is read by only 2 warps: LDS reads per
// CTA-iter drop 48KB -> 32KB while tensor work is unchanged.
// SMEM rows 80B (conflict-free ldmatrix: 16B-unit index r*5 mod 8 permutes
// 8 rows). 3-stage cp.async ring, one bar per iter.
// B-fragment pairing: ldmatrix.x4 gives bb[0]=rows0-7@c, bb[1]=rows8-15@c,
// bb[2]=rows0-7@c+16, bb[3]=rows8-15@c+16; the m16n8k16 B frag is
// (row-half @ k-lo, row-half @ k-hi) = (bb[h], bb[2+h]).
#define PITCH 80
#define TILEB (128 * PITCH)
#define SMEMSZ (6 * TILEB)        // 3 stages x (A + B) = 61440 B
#define NT 128                    // threads per CTA

template <typename EpiF>
__device__ __forceinline__ void gemm_core(
    const bf16* __restrict__ A, int ldA,
    const bf16* __restrict__ Bm, int ldB,
    int K, int kk0, int niter, int m0, int n0,
    uint32_t sbase, int tid, EpiF&& epi)
{
    const int lane = tid & 31;
    const int w    = tid >> 5;        // 0..3
    const int wm   = w >> 1;          // 0..1
    const int wn   = w & 1;           // 0..1
    const int g    = lane >> 2;
    const int t    = lane & 3;

    // cp.async mapping: 512 x 16B chunks per operand, 4 per thread
    const int c0c = (tid & 3) * 16;   // byte chunk within 64B row

    float acc[4][8][4];
#pragma unroll
    for (int i = 0; i < 4; i++)
#pragma unroll
        for (int j = 0; j < 8; j++)
#pragma unroll
            for (int q = 0; q < 4; q++) acc[i][j][q] = 0.f;

    const int lrow = lane & 15;
    const int lcol = (lane >> 4) * 16;

    auto issue = [&](int it) {
        int ka, kb; koffs(kk0 + it * 32, K, ka, kb);
        const bf16* pa = A  + ka + c0c / 2;
        const bf16* pb = Bm + kb + c0c / 2;
        const uint32_t da = sbase + (it % 3) * TILEB;
        const uint32_t db = sbase + 3 * TILEB + (it % 3) * TILEB;
#pragma unroll
        for (int i = 0; i < 4; i++) {
            int r = (tid >> 2) + i * 32;
            cp_async16(da + r * PITCH + c0c, pa + (size_t)(m0 + r) * ldA);
            cp_async16(db + r * PITCH + c0c, pb + (size_t)(n0 + r) * ldB);
        }
    };

    issue(0); cp_commit();
    issue(1); cp_commit();

    for (int it = 0; it < niter; it++) {
        cp_wait<1>();          // tile `it` landed (one group per iter, uniform)
        __syncthreads();       // reads of tile it-1 done -> stage (it+2)%3 free
        if (it + 2 < niter) issue(it + 2);
        cp_commit();           // empty tail groups keep the count uniform

        const uint32_t ca = sbase + (it % 3) * TILEB;
        const uint32_t cb = sbase + 3 * TILEB + (it % 3) * TILEB;
#pragma unroll
        for (int s = 0; s < 2; s++) {
            const int cbyte = s * 32 + lcol;
            unsigned af[4][4];
#pragma unroll
            for (int mt = 0; mt < 4; mt++)
                ldmx4(af[mt], ca + (wm * 64 + mt * 16 + lrow) * PITCH + cbyte);
#pragma unroll
            for (int p = 0; p < 4; p++) {
                unsigned bb[4];
                ldmx4(bb, cb + (wn * 64 + p * 16 + lrow) * PITCH + cbyte);
#pragma unroll
                for (int mt = 0; mt < 4; mt++) {
                    mma16816(acc[mt][2 * p + 0], af[mt], bb[0], bb[2]);
                    mma16816(acc[mt][2 * p + 1], af[mt], bb[1], bb[3]);
                }
            }
        }
    }

#pragma unroll
    for (int mt = 0; mt < 4; mt++) {
#pragma unroll
        for (int nt = 0; nt < 8; nt++) {
            float* ac = acc[mt][nt];
            const int m = m0 + wm * 64 + mt * 16 + g;
            const int n = n0 + wn * 64 + nt * 8 + 2 * t;
#pragma unroll
            for (int h = 0; h < 2; h++)
                epi(m + h * 8, n, ac[2 * h + 0], ac[2 * h + 1]);
        }
    }
}

// ---- qv GEMM: q|v projections (512 CTAs) ----
__global__ __launch_bounds__(NT, 2) void mm_qv()
{
    extern __shared__ char dyns[];
    const uint32_t sbase = smem_u32(dyns);
    const int tid = threadIdx.x;
    const int b   = blockIdx.z;
    const int m0  = blockIdx.y * 128;
    const int n0  = blockIdx.x * 128;

    gemm_core(g_Ws, 512, g_xs + (size_t)b * NN * 512, 512, CC, 0, 24,
              m0, n0, sbase, tid,
        [&](int mr, int n, float v0, float v1) {
            const float bia = g_bias[mr];
            v0 += bia; v1 += bia;
            const int proj = mr >> 8;       // 0=q, 1=v (uniform per CTA)
            const int ml   = mr & 255;
            bf16* row = (proj ? g_vs : g_qs) + (size_t)(b * CC + ml) * 2 * NN;
            split_store(row, n, NN, v0, v1);
        });
}

// ---- fused kT + vq GEMM (640 CTAs, sequential ranges) ----
// bid [0,384):  vq  M = V Q^T, split-K 12 -> Mpart
// bid [384,640): kT  k^T = x^T Wk^T       -> ksT split
__global__ __launch_bounds__(NT, 2) void mm_ktvq()
{
    extern __shared__ char dyns[];
    const uint32_t sbase = smem_u32(dyns);
    const int tid = threadIdx.x;
    const int bid = blockIdx.x;

    if (bid < 384) {
        const int bz = bid >> 2;            // 0..95 = b*12+ch
        const int b  = bz / 12;
        const int ch = bz - 12 * b;
        const int m0 = ((bid >> 1) & 1) * 128;
        const int n0 = (bid & 1) * 128;
        const bf16* A  = g_vs + (size_t)b * CC * 2 * NN;
        const bf16* Bm = g_qs + (size_t)b * CC * 2 * NN;
        gemm_core(A, 2 * NN, Bm, 2 * NN, NN, ch * 512, 16, m0, n0, sbase, tid,
            [&](int mr, int n, float v0, float v1) {
                *(float2*)&g_Mpart[((size_t)bz * CC + mr) * CC + n] =
                    make_float2(v0, v1);
            });
    } else {
        const int idx = bid - 384;          // 0..255
        const int b   = idx >> 5;
        const int rem = idx & 31;
        const int m0  = (rem >> 1) * 128;   // token tile
        const int n0  = (rem & 1) * 128;    // channel tile
        const bf16* A  = g_xs + (size_t)b * NN * 512;
        const bf16* Bm = g_Ws + (size_t)512 * 512;
        gemm_core(A, 512, Bm, 512, CC, 0, 24, m0, n0, sbase, tid,
            [&](int mr, int n, float v0, float v1) {
                v0 += g_bias[512 + n];
                v1 += g_bias[512 + n + 1];
                bf16* row = g_ksT + (size_t)(b * NN + mr) * 512;
                split_store(row, n, CC, v0, v1);
            });
    }
}

// ---- out GEMM: out = (M K^T) * (1/S); 1/S computed per-CTA from g_spart ----
__global__ __launch_bounds__(NT, 2) void mm_out(float* __restrict__ dout)
{
    extern __shared__ char dyns[];
    const uint32_t sbase = smem_u32(dyns);
    const int tid  = threadIdx.x;
    const int lane = tid & 31;
    const int w    = tid >> 5;
    const int b    = blockIdx.z;
    const int m0   = blockIdx.y * 128;
    const int n0   = blockIdx.x * 128;

    // per-CTA deterministic 1/S (identical in every CTA); uses dyn smem
    // BEFORE the pipeline prologue touches it.
    float inv;
    {
        double acc = 0.0;
        for (int i = tid; i < BB * CC; i += NT) acc += (double)g_spart[i];
#pragma unroll
        for (int off = 16; off > 0; off >>= 1)
            acc += __shfl_down_sync(0xFFFFFFFFu, acc, off);
        double* red = (double*)dyns;
        if (lane == 0) red[w] = acc;
        __syncthreads();
        double s = 0.0;
#pragma unroll
        for (int i = 0; i < 4; i++) s += red[i];
        inv = (float)(1.0 / s);
        __syncthreads();
    }

    gemm_core(g_Ms + (size_t)b * CC * 512, 512,
              g_ksT + (size_t)b * NN * 512, 512, CC, 0, 24,
              m0, n0, sbase, tid,
        [&](int mr, int n, float v0, float v1) {
            *(float2*)&dout[(size_t)(b * CC + mr) * NN + n] =
                make_float2(v0 * inv, v1 * inv);
        });
}

// ------------------------- prep / reduction kernels -------------------------

// W rows reordered [q|v|k], split to bf16 hi/lo; bias same order.
// Blocks 0..BB-1 also zero g_xsum (runs BEFORE transpose_split).
__global__ void wprep_kernel(const float* __restrict__ Wq, const float* __restrict__ bq,
                             const float* __restrict__ Wk, const float* __restrict__ bk,
                             const float* __restrict__ Wv, const float* __restrict__ bv)
{
    const int m = blockIdx.x;       // 0..767
    const int c = threadIdx.x;      // 0..255
    if (m < BB) g_xsum[m * CC + c] = 0.f;
    const float* Wsrc = (m < CC) ? Wq : (m < 2 * CC) ? Wv : Wk;
    const int ml = m & (CC - 1);
    const float v = Wsrc[ml * CC + c];
    const bf16 hi = __float2bfloat16(v);
    g_Ws[(size_t)m * 512 + c]       = hi;
    g_Ws[(size_t)m * 512 + CC + c]  = __float2bfloat16(v - __bfloat162float(hi));
    if (c == 0) g_bias[m] = (m < CC) ? bq[ml] : (m < 2 * CC) ? bv[ml] : bk[ml];
}

// x [b][C][N] fp32 -> g_xs [b][n][hiC|loC]; also accumulate xsum[b][c]
__global__ void transpose_split_kernel(const float* __restrict__ x)
{
    __shared__ float tile[32][33];
    const int b  = blockIdx.z;
    const int c0 = blockIdx.y * 32;
    const int n0 = blockIdx.x * 32;
    const float* S = x + (size_t)b * CC * NN;
    bf16* D = g_xs + (size_t)b * NN * 2 * CC;

#pragma unroll
    for (int i = 0; i < 4; i++)
        tile[threadIdx.y + i * 8][threadIdx.x] =
            S[(size_t)(c0 + threadIdx.y + i * 8) * NN + n0 + threadIdx.x];
    __syncthreads();

    if (threadIdx.y == 0) {
        float s = 0.f;
#pragma unroll
        for (int i = 0; i < 32; i++) s += tile[threadIdx.x][i];
        atomicAdd(&g_xsum[b * CC + c0 + threadIdx.x], s);
    }
#pragma unroll
    for (int i = 0; i < 4; i++) {
        const int n = n0 + threadIdx.y + i * 8;
        const int c = c0 + threadIdx.x;
        const float v = tile[threadIdx.x][threadIdx.y + i * 8];
        const bf16 hi = __float2bfloat16(v);
        D[(size_t)n * 2 * CC + c]      = hi;
        D[(size_t)n * 2 * CC + CC + c] = __float2bfloat16(v - __bfloat162float(hi));
    }
}

// Fused: blocks [0,2048): reduce 12 split-K chunks -> M split bf16.
//        blocks [2048,2304): spart[b,c] = (Wq[c]·xs_b + N·bq)·(Wk[c]·xs_b + N·bk)
__global__ __launch_bounds__(256) void mreduce_spartial_kernel(
    const float* __restrict__ Wq, const float* __restrict__ bq,
    const float* __restrict__ Wk, const float* __restrict__ bk)
{
    const int bid = blockIdx.x;
    if (bid < 2048) {
        const int b  = bid >> 8;
        const int c1 = bid & 255;
        const int c2 = threadIdx.x;
        float s = 0.f;
#pragma unroll
        for (int ch = 0; ch < 12; ch++)
            s += g_Mpart[((size_t)(b * 12 + ch) * CC + c1) * CC + c2];
        const bf16 hi = __float2bfloat16(s);
        g_Ms[(size_t)(b * CC + c1) * 512 + c2]      = hi;
        g_Ms[(size_t)(b * CC + c1) * 512 + CC + c2] = __float2bfloat16(s - __bfloat162float(hi));
    } else {
        __shared__ float xs[CC];
        const int idx  = bid - 2048;            // 0..255
        const int b    = idx >> 5;
        const int tid  = threadIdx.x;
        const int lane = tid & 31;
        const int w    = tid >> 5;
        const int c    = (idx & 31) * 8 + w;

        xs[tid] = g_xsum[b * CC + tid];
        __syncthreads();

        float qd = 0.f, kd = 0.f;
#pragma unroll
        for (int j = lane; j < CC; j += 32) {
            const float xv = xs[j];
            qd += Wq[c * CC + j] * xv;
            kd += Wk[c * CC + j] * xv;
        }
#pragma unroll
        for (int off = 16; off > 0; off >>= 1) {
            qd += __shfl_down_sync(0xFFFFFFFFu, qd, off);
            kd += __shfl_down_sync(0xFFFFFFFFu, kd, off);
        }
        if (lane == 0) {
            qd += (float)NN * bq[c];
            kd += (float)NN * bk[c];
            g_spart[b * CC + c] = qd * kd;
        }
    }
}

// ------------------------- launch -------------------------
extern "C" void kernel_launch(void* const* d_in, const int* in_sizes, int n_in,
                              void* d_out, int out_size)
{
    const float* x  = (const float*)d_in[0];
    const float* Wq = (const float*)d_in[1];
    const float* bq = (const float*)d_in[2];
    const float* Wk = (const float*)d_in[3];
    const float* bk = (const float*)d_in[4];
    const float* Wv = (const float*)d_in[5];
    const float* bv = (const float*)d_in[6];
    float* out = (float*)d_out;

    cudaFuncSetAttribute(mm_qv,   cudaFuncAttributeMaxDynamicSharedMemorySize, SMEMSZ);
    cudaFuncSetAttribute(mm_ktvq, cudaFuncAttributeMaxDynamicSharedMemorySize, SMEMSZ);
    cudaFuncSetAttribute(mm_out,  cudaFuncAttributeMaxDynamicSharedMemorySize, SMEMSZ);

    wprep_kernel<<<3 * CC, 256>>>(Wq, bq, Wk, bk, Wv, bv);  // also zeroes xsum
    transpose_split_kernel<<<dim3(NN / 32, CC / 32, BB), dim3(32, 8)>>>(x);

    // q|v projections: M=512, N=2048 per b (512 CTAs)
    mm_qv<<<dim3(16, 4, BB), NT, SMEMSZ>>>();
    // fused: vq split-K 12 (384 CTAs) + k^T (256 CTAs) in one launch
    mm_ktvq<<<640, NT, SMEMSZ>>>();
    // reduce M partials + compute S partials (independent halves of one launch)
    mreduce_spartial_kernel<<<2048 + 256, 256>>>(Wq, bq, Wk, bk);
    // out = (M K^T) / S   (each CTA derives 1/S deterministically)
    mm_out<<<dim3(16, 2, BB), NT, SMEMSZ>>>(out);
}

// round 17
// speedup vs baseline: 1.1607x; 1.1607x over previous
#include <cuda_runtime.h>
#include <cuda_bf16.h>
#include <cstdint>

#define BB 8
#define CC 256
#define NN 2048

typedef __nv_bfloat16 bf16;

// ------------------------- scratch (device globals) -------------------------
__device__ bf16  g_xs [BB * NN * 2 * CC];   // x split  [b][n][hiC|loC]
__device__ bf16  g_Ws [3 * CC * 2 * CC];    // W split rows [q|v|k], [m][hiC|loC]
__device__ float g_bias[3 * CC];            // [q|v|k]
__device__ bf16  g_qs [BB * CC * 2 * NN];   // q split  [b*C+c][hiN|loN]
__device__ bf16  g_vs [BB * CC * 2 * NN];   // v split
__device__ float g_Mpart[96 * CC * CC];     // split-K partials (12 chunks x 8 b)
__device__ bf16  g_Ms [BB * CC * 2 * CC];   // M split  [b*C+c1][hiC2|loC2]
__device__ bf16  g_WkTs[CC * 2 * CC];       // Wk^T split [c2][hiC|loC] (= Wk[c][c2])
__device__ bf16  g_M2s[BB * CC * 2 * CC];   // M2 = (M Wk)/S split [b*C+c1][hiC2|loC2]
__device__ float g_mb [BB * CC];            // mb[b,c1] = sum_c M[b][c1][c] * bk[c]
__device__ float g_xsum[BB * CC];
__device__ float g_spart[BB * CC];

// ------------------------- helpers -------------------------
__device__ __forceinline__ uint32_t smem_u32(const void* p) {
    uint32_t a;
    asm("{ .reg .u64 t; cvta.to.shared.u64 t, %1; cvt.u32.u64 %0, t; }" : "=r"(a) : "l"(p));
    return a;
}

__device__ __forceinline__ void cp_async16(uint32_t saddr, const void* gaddr) {
    asm volatile("cp.async.cg.shared.global [%0], [%1], 16;\n" :: "r"(saddr), "l"(gaddr));
}
__device__ __forceinline__ void cp_commit() {
    asm volatile("cp.async.commit_group;\n" ::: "memory");
}
template <int N>
__device__ __forceinline__ void cp_wait() {
    asm volatile("cp.async.wait_group %0;\n" :: "n"(N) : "memory");
}

__device__ __forceinline__ void ldmx4(unsigned* r, uint32_t addr) {
    asm volatile("ldmatrix.sync.aligned.m8n8.x4.shared.b16 {%0,%1,%2,%3}, [%4];\n"
                 : "=r"(r[0]), "=r"(r[1]), "=r"(r[2]), "=r"(r[3]) : "r"(addr));
}

__device__ __forceinline__ void mma16816(float* c, const unsigned* a,
                                         unsigned b0, unsigned b1) {
    asm volatile(
        "mma.sync.aligned.m16n8k16.row.col.f32.bf16.bf16.f32 "
        "{%0,%1,%2,%3},{%4,%5,%6,%7},{%8,%9},{%0,%1,%2,%3};\n"
        : "+f"(c[0]), "+f"(c[1]), "+f"(c[2]), "+f"(c[3])
        : "r"(a[0]), "r"(a[1]), "r"(a[2]), "r"(a[3]), "r"(b0), "r"(b1));
}

// split-bf16 K'' -> (ka, kb): t0: hi*hi, t1: Ahi*Blo, t2: Alo*Bhi
__device__ __forceinline__ void koffs(int kk, int K, int& ka, int& kb) {
    int term = kk / K;
    int kmod = kk - term * K;
    ka = (term == 2 ? K : 0) + kmod;
    kb = (term == 1 ? K : 0) + kmod;
}

__device__ __forceinline__ void split_store(bf16* row, int n, int lo_off,
                                            float v0, float v1)
{
    __nv_bfloat162 h, l;
    h.x = __float2bfloat16(v0);
    h.y = __float2bfloat16(v1);
    l.x = __float2bfloat16(v0 - __bfloat162float(h.x));
    l.y = __float2bfloat16(v1 - __bfloat162float(h.y));
    *reinterpret_cast<__nv_bfloat162*>(row + n)          = h;
    *reinterpret_cast<__nv_bfloat162*>(row + lo_off + n) = l;
}

// per-CTA deterministic 1/S from g_spart (identical in every CTA).
// Uses the dynamic smem briefly BEFORE the pipeline prologue touches it.
__device__ __forceinline__ float compute_inv(char* dyns, int tid)
{
    const int lane = tid & 31;
    const int w    = tid >> 5;
    double acc = 0.0;
    for (int i = tid; i < BB * CC; i += 256) acc += (double)g_spart[i];
#pragma unroll
    for (int off = 16; off > 0; off >>= 1)
        acc += __shfl_down_sync(0xFFFFFFFFu, acc, off);
    double* red = (double*)dyns;
    if (lane == 0) red[w] = acc;
    __syncthreads();
    double s = 0.0;
#pragma unroll
    for (int i = 0; i < 8; i++) s += red[i];
    float inv = (float)(1.0 / s);
    __syncthreads();
    return inv;
}

// ------------------------- mma.sync GEMM core (R13-best) -------------------------
// BM=128, BN=128, BK=32 bf16, 256 threads (8 warps, 2x4), warp tile 64x32.
// SMEM rows 80B (conflict-free ldmatrix: 16B-unit index r*5 mod 8 permutes
// 8 rows). 3-stage cp.async ring, one bar per iter.
#define PITCH 80
#define TILEB (128 * PITCH)
#define SMEMSZ (6 * TILEB)        // 3 stages x (A + B) = 61440 B

template <typename EpiF>
__device__ __forceinline__ void gemm_core(
    const bf16* __restrict__ A, int ldA,
    const bf16* __restrict__ Bm, int ldB,
    int K, int kk0, int niter, int m0, int n0,
    uint32_t sbase, int tid, EpiF&& epi)
{
    const int lane = tid & 31;
    const int w    = tid >> 5;
    const int wm   = w >> 2;
    const int wn   = w & 3;
    const int g    = lane >> 2;
    const int t    = lane & 3;

    const int r0c = tid >> 2;                 // rows tid>>2 and +64
    const int c0c = (tid & 3) * 16;           // byte chunk within 64B row

    float acc[4][4][4];
#pragma unroll
    for (int i = 0; i < 4; i++)
#pragma unroll
        for (int j = 0; j < 4; j++)
#pragma unroll
            for (int q = 0; q < 4; q++) acc[i][j][q] = 0.f;

    const int lrow = lane & 15;
    const int lcol = (lane >> 4) * 16;

    auto issue = [&](int it) {
        int ka, kb; koffs(kk0 + it * 32, K, ka, kb);
        const bf16* pa = A  + ka + c0c / 2;
        const bf16* pb = Bm + kb + c0c / 2;
        const uint32_t da = sbase + (it % 3) * TILEB;
        const uint32_t db = sbase + 3 * TILEB + (it % 3) * TILEB;
#pragma unroll
        for (int i = 0; i < 2; i++) {
            int r = r0c + i * 64;
            cp_async16(da + r * PITCH + c0c, pa + (size_t)(m0 + r) * ldA);
            cp_async16(db + r * PITCH + c0c, pb + (size_t)(n0 + r) * ldB);
        }
    };

    issue(0); cp_commit();
    issue(1); cp_commit();

    for (int it = 0; it < niter; it++) {
        cp_wait<1>();          // tile `it` landed (one group per iter, uniform)
        __syncthreads();       // reads of tile it-1 done -> stage (it+2)%3 free
        if (it + 2 < niter) issue(it + 2);
        cp_commit();           // empty tail groups keep the count uniform

        const uint32_t ca = sbase + (it % 3) * TILEB;
        const uint32_t cb = sbase + 3 * TILEB + (it % 3) * TILEB;
#pragma unroll
        for (int s = 0; s < 2; s++) {
            const int cbyte = s * 32 + lcol;
            unsigned af[4][4];
#pragma unroll
            for (int mt = 0; mt < 4; mt++)
                ldmx4(af[mt], ca + (wm * 64 + mt * 16 + lrow) * PITCH + cbyte);
            unsigned bb[2][4];
#pragma unroll
            for (int p = 0; p < 2; p++)
                ldmx4(bb[p], cb + (wn * 32 + p * 16 + lrow) * PITCH + cbyte);
#pragma unroll
            for (int mt = 0; mt < 4; mt++)
#pragma unroll
                for (int nt = 0; nt < 4; nt++)
                    mma16816(acc[mt][nt], af[mt],
                             bb[nt >> 1][nt & 1], bb[nt >> 1][2 + (nt & 1)]);
        }
    }

#pragma unroll
    for (int mt = 0; mt < 4; mt++) {
#pragma unroll
        for (int nt = 0; nt < 4; nt++) {
            float* ac = acc[mt][nt];
            const int m = m0 + wm * 64 + mt * 16 + g;
            const int n = n0 + wn * 32 + nt * 8 + 2 * t;
#pragma unroll
            for (int h = 0; h < 2; h++)
                epi(m + h * 8, n, ac[2 * h + 0], ac[2 * h + 1]);
        }
    }
}

// ---- qv GEMM: q|v projections (512 CTAs) ----
__global__ __launch_bounds__(256, 2) void mm_qv()
{
    extern __shared__ char dyns[];
    const uint32_t sbase = smem_u32(dyns);
    const int tid = threadIdx.x;
    const int b   = blockIdx.z;
    const int m0  = blockIdx.y * 128;
    const int n0  = blockIdx.x * 128;

    gemm_core(g_Ws, 512, g_xs + (size_t)b * NN * 512, 512, CC, 0, 24,
              m0, n0, sbase, tid,
        [&](int mr, int n, float v0, float v1) {
            const float bia = g_bias[mr];
            v0 += bia; v1 += bia;
            const int proj = mr >> 8;       // 0=q, 1=v (uniform per CTA)
            const int ml   = mr & 255;
            bf16* row = (proj ? g_vs : g_qs) + (size_t)(b * CC + ml) * 2 * NN;
            split_store(row, n, NN, v0, v1);
        });
}

// ---- vq GEMM: M = V Q^T, split-K 12 -> Mpart (384 CTAs) ----
__global__ __launch_bounds__(256, 2) void mm_vq()
{
    extern __shared__ char dyns[];
    const uint32_t sbase = smem_u32(dyns);
    const int tid = threadIdx.x;
    const int bz  = blockIdx.z;           // b*12 + ch
    const int b   = bz / 12;
    const int ch  = bz - 12 * b;
    const int m0  = blockIdx.y * 128;
    const int n0  = blockIdx.x * 128;

    const bf16* A  = g_vs + (size_t)b * CC * 2 * NN;
    const bf16* Bm = g_qs + (size_t)b * CC * 2 * NN;
    gemm_core(A, 2 * NN, Bm, 2 * NN, NN, ch * 512, 16, m0, n0, sbase, tid,
        [&](int mr, int n, float v0, float v1) {
            *(float2*)&g_Mpart[((size_t)bz * CC + mr) * CC + n] =
                make_float2(v0, v1);
        });
}

// ---- m2 GEMM: M2 = (M Wk) * (1/S) -> split (32 CTAs) ----
__global__ __launch_bounds__(256, 2) void mm_m2()
{
    extern __shared__ char dyns[];
    const uint32_t sbase = smem_u32(dyns);
    const int tid = threadIdx.x;
    const int b   = blockIdx.z;
    const int m0  = blockIdx.y * 128;
    const int n0  = blockIdx.x * 128;

    const float inv = compute_inv(dyns, tid);

    gemm_core(g_Ms + (size_t)b * CC * 512, 512, g_WkTs, 512, CC, 0, 24,
              m0, n0, sbase, tid,
        [&](int mr, int n, float v0, float v1) {
            split_store(g_M2s + (size_t)(b * CC + mr) * 512, n, CC,
                        v0 * inv, v1 * inv);
        });
}

// ---- out GEMM: out = M2 x + (mb/S) (256 CTAs) ----
__global__ __launch_bounds__(256, 2) void mm_out(float* __restrict__ dout)
{
    extern __shared__ char dyns[];
    const uint32_t sbase = smem_u32(dyns);
    const int tid = threadIdx.x;
    const int b   = blockIdx.z;
    const int m0  = blockIdx.y * 128;
    const int n0  = blockIdx.x * 128;

    const float inv = compute_inv(dyns, tid);

    gemm_core(g_M2s + (size_t)b * CC * 512, 512,
              g_xs + (size_t)b * NN * 512, 512, CC, 0, 24,
              m0, n0, sbase, tid,
        [&](int mr, int n, float v0, float v1) {
            const float mbv = g_mb[b * CC + mr] * inv;
            *(float2*)&dout[(size_t)(b * CC + mr) * NN + n] =
                make_float2(v0 + mbv, v1 + mbv);
        });
}

// ------------------------- prep / reduction kernels -------------------------

// Blocks [0,768): W rows reordered [q|v|k], split bf16 hi/lo; bias; blocks
// 0..BB-1 also zero g_xsum. Blocks [768,832): Wk^T tile-transpose + split.
__global__ void wprep_kernel(const float* __restrict__ Wq, const float* __restrict__ bq,
                             const float* __restrict__ Wk, const float* __restrict__ bk,
                             const float* __restrict__ Wv, const float* __restrict__ bv)
{
    __shared__ float tile[32][33];
    const int m = blockIdx.x;
    const int c = threadIdx.x;      // 0..255

    if (m >= 768) {
        // Wk^T split: g_WkTs[c2][c] = Wk[c][c2]
        const int idx = m - 768;            // 0..63
        const int c0  = (idx & 7) * 32;     // Wk row tile
        const int t0  = (idx >> 3) * 32;    // Wk col tile
        const int tx = c & 31, ty = c >> 5; // 32 x 8
#pragma unroll
        for (int i = 0; i < 4; i++)
            tile[ty + i * 8][tx] = Wk[(c0 + ty + i * 8) * CC + t0 + tx];
        __syncthreads();
#pragma unroll
        for (int i = 0; i < 4; i++) {
            const int c2 = t0 + ty + i * 8;
            const int cc = c0 + tx;
            const float v = tile[tx][ty + i * 8];
            const bf16 hi = __float2bfloat16(v);
            g_WkTs[(size_t)c2 * 512 + cc]      = hi;
            g_WkTs[(size_t)c2 * 512 + CC + cc] = __float2bfloat16(v - __bfloat162float(hi));
        }
        return;
    }

    if (m < BB) g_xsum[m * CC + c] = 0.f;
    const float* Wsrc = (m < CC) ? Wq : (m < 2 * CC) ? Wv : Wk;
    const int ml = m & (CC - 1);
    const float v = Wsrc[ml * CC + c];
    const bf16 hi = __float2bfloat16(v);
    g_Ws[(size_t)m * 512 + c]       = hi;
    g_Ws[(size_t)m * 512 + CC + c]  = __float2bfloat16(v - __bfloat162float(hi));
    if (c == 0) g_bias[m] = (m < CC) ? bq[ml] : (m < 2 * CC) ? bv[ml] : bk[ml];
}

// x [b][C][N] fp32 -> g_xs [b][n][hiC|loC]; also accumulate xsum[b][c]
__global__ void transpose_split_kernel(const float* __restrict__ x)
{
    __shared__ float tile[32][33];
    const int b  = blockIdx.z;
    const int c0 = blockIdx.y * 32;
    const int n0 = blockIdx.x * 32;
    const float* S = x + (size_t)b * CC * NN;
    bf16* D = g_xs + (size_t)b * NN * 2 * CC;

#pragma unroll
    for (int i = 0; i < 4; i++)
        tile[threadIdx.y + i * 8][threadIdx.x] =
            S[(size_t)(c0 + threadIdx.y + i * 8) * NN + n0 + threadIdx.x];
    __syncthreads();

    if (threadIdx.y == 0) {
        float s = 0.f;
#pragma unroll
        for (int i = 0; i < 32; i++) s += tile[threadIdx.x][i];
        atomicAdd(&g_xsum[b * CC + c0 + threadIdx.x], s);
    }
#pragma unroll
    for (int i = 0; i < 4; i++) {
        const int n = n0 + threadIdx.y + i * 8;
        const int c = c0 + threadIdx.x;
        const float v = tile[threadIdx.x][threadIdx.y + i * 8];
        const bf16 hi = __float2bfloat16(v);
        D[(size_t)n * 2 * CC + c]      = hi;
        D[(size_t)n * 2 * CC + CC + c] = __float2bfloat16(v - __bfloat162float(hi));
    }
}

// Fused: blocks [0,2048): reduce 12 split-K chunks -> M split bf16 + mb = M·bk.
//        blocks [2048,2304): spart[b,c] = (Wq[c]·xs_b + N·bq)·(Wk[c]·xs_b + N·bk)
__global__ __launch_bounds__(256) void mreduce_spartial_kernel(
    const float* __restrict__ Wq, const float* __restrict__ bq,
    const float* __restrict__ Wk, const float* __restrict__ bk)
{
    const int bid = blockIdx.x;
    if (bid < 2048) {
        const int b  = bid >> 8;
        const int c1 = bid & 255;
        const int c2 = threadIdx.x;
        float s = 0.f;
#pragma unroll
        for (int ch = 0; ch < 12; ch++)
            s += g_Mpart[((size_t)(b * 12 + ch) * CC + c1) * CC + c2];
        const bf16 hi = __float2bfloat16(s);
        g_Ms[(size_t)(b * CC + c1) * 512 + c2]      = hi;
        g_Ms[(size_t)(b * CC + c1) * 512 + CC + c2] = __float2bfloat16(s - __bfloat162float(hi));
        // mb[b,c1] = sum_c2 M[b][c1][c2] * bk[c2]  (deterministic tree)
        __shared__ float red[256];
        red[c2] = s * bk[c2];
        __syncthreads();
        for (int st = 128; st > 0; st >>= 1) {
            if (c2 < st) red[c2] += red[c2 + st];
            __syncthreads();
        }
        if (c2 == 0) g_mb[b * CC + c1] = red[0];
    } else {
        __shared__ float xs[CC];
        const int idx  = bid - 2048;            // 0..255
        const int b    = idx >> 5;
        const int tid  = threadIdx.x;
        const int lane = tid & 31;
        const int w    = tid >> 5;
        const int c    = (idx & 31) * 8 + w;

        xs[tid] = g_xsum[b * CC + tid];
        __syncthreads();

        float qd = 0.f, kd = 0.f;
#pragma unroll
        for (int j = lane; j < CC; j += 32) {
            const float xv = xs[j];
            qd += Wq[c * CC + j] * xv;
            kd += Wk[c * CC + j] * xv;
        }
#pragma unroll
        for (int off = 16; off > 0; off >>= 1) {
            qd += __shfl_down_sync(0xFFFFFFFFu, qd, off);
            kd += __shfl_down_sync(0xFFFFFFFFu, kd, off);
        }
        if (lane == 0) {
            qd += (float)NN * bq[c];
            kd += (float)NN * bk[c];
            g_spart[b * CC + c] = qd * kd;
        }
    }
}

// ------------------------- launch -------------------------
extern "C" void kernel_launch(void* const* d_in, const int* in_sizes, int n_in,
                              void* d_out, int out_size)
{
    const float* x  = (const float*)d_in[0];
    const float* Wq = (const float*)d_in[1];
    const float* bq = (const float*)d_in[2];
    const float* Wk = (const float*)d_in[3];
    const float* bk = (const float*)d_in[4];
    const float* Wv = (const float*)d_in[5];
    const float* bv = (const float*)d_in[6];
    float* out = (float*)d_out;

    cudaFuncSetAttribute(mm_qv,  cudaFuncAttributeMaxDynamicSharedMemorySize, SMEMSZ);
    cudaFuncSetAttribute(mm_vq,  cudaFuncAttributeMaxDynamicSharedMemorySize, SMEMSZ);
    cudaFuncSetAttribute(mm_m2,  cudaFuncAttributeMaxDynamicSharedMemorySize, SMEMSZ);
    cudaFuncSetAttribute(mm_out, cudaFuncAttributeMaxDynamicSharedMemorySize, SMEMSZ);

    // W split + bias + Wk^T split + zero xsum
    wprep_kernel<<<3 * CC + 64, 256>>>(Wq, bq, Wk, bk, Wv, bv);
    transpose_split_kernel<<<dim3(NN / 32, CC / 32, BB), dim3(32, 8)>>>(x);

    // q|v projections: M=512, N=2048 per b (512 CTAs)
    mm_qv<<<dim3(16, 4, BB), 256, SMEMSZ>>>();
    // M = V Q^T, split-K 12 (384 CTAs)
    mm_vq<<<dim3(2, 2, BB * 12), 256, SMEMSZ>>>();
    // reduce M partials (+ mb = M·bk) + compute S partials
    mreduce_spartial_kernel<<<2048 + 256, 256>>>(Wq, bq, Wk, bk);
    // M2 = (M Wk)/S  (32 CTAs)
    mm_m2<<<dim3(2, 2, BB), 256, SMEMSZ>>>();
    // out = M2 x + mb/S  (256 CTAs)
    mm_out<<<dim3(16, 2, BB), 256, SMEMSZ>>>(out);
}